// round 15
// baseline (speedup 1.0000x reference)
#include <cuda_runtime.h>
#include <cuda_bf16.h>
#include <math.h>

#define NN 512
#define NBATCH 128
#define EPS 1e-8f
#define S_CAP 304
#define PK_CAP ((S_CAP*(S_CAP+1))/2)      /* 46360 floats */
#define PBW_SM (S_CAP-32)                  /* 272 */
#define PK_FULL ((NN*(NN+1))/2)
#define NTB 512
#define NWB 16
#define DYN_B ((PK_CAP + 32*PBW_SM)*4)    /* 220256 B */
#define ZPBW 488                           /* zbig PB row width (480 used + pad) */
#define ZB_SMEM (32*ZPBW*4)               /* 62464 B */

// ---------------- device scratch ----------------
__device__ float g_L[NN*NN];
__device__ float g_Z[NN*NN];               // L + I, factored in place (lower)
__device__ float g_zlog;                   // logdet(L+I)
__device__ float g_bres[NBATCH];
__device__ __align__(16) float g_fbA[(size_t)NBATCH * PK_FULL];
__device__ __align__(16) float g_fbPB[(size_t)NBATCH * 32 * NN];

// =====================================================================
// K1: L = B^T B + eps I ; Z = L + I.
// =====================================================================
__global__ __launch_bounds__(256) void k_gemm(const float* __restrict__ B)
{
    __shared__ float SA[16][64];
    __shared__ float SB[16][64];
    const int tid = threadIdx.x;
    const int tx = tid & 15, ty = tid >> 4;
    const int i0 = blockIdx.y * 64, j0 = blockIdx.x * 64;

    float acc[4][4];
#pragma unroll
    for (int r = 0; r < 4; ++r)
#pragma unroll
        for (int c = 0; c < 4; ++c) acc[r][c] = 0.f;

    for (int kc = 0; kc < NN; kc += 16) {
        for (int e = tid; e < 16*64; e += 256) {
            int kk = e >> 6, ii = e & 63;
            SA[kk][ii] = B[(kc+kk)*NN + i0 + ii];
            SB[kk][ii] = B[(kc+kk)*NN + j0 + ii];
        }
        __syncthreads();
#pragma unroll
        for (int kk = 0; kk < 16; ++kk) {
            float a[4], bb[4];
#pragma unroll
            for (int r = 0; r < 4; ++r) a[r]  = SA[kk][ty*4 + r];
#pragma unroll
            for (int c = 0; c < 4; ++c) bb[c] = SB[kk][tx*4 + c];
#pragma unroll
            for (int r = 0; r < 4; ++r)
#pragma unroll
                for (int c = 0; c < 4; ++c) acc[r][c] += a[r] * bb[c];
        }
        __syncthreads();
    }
#pragma unroll
    for (int r = 0; r < 4; ++r)
#pragma unroll
        for (int c = 0; c < 4; ++c) {
            int gi = i0 + ty*4 + r, gj = j0 + tx*4 + c;
            float v = acc[r][c] + ((gi == gj) ? EPS : 0.f);
            g_L[gi*NN + gj] = v;
            g_Z[gi*NN + gj] = v + ((gi == gj) ? 1.f : 0.f);
        }
}

// =====================================================================
// Per-batch blocked Cholesky (nb=32), 512 threads. (unchanged)
// =====================================================================
__global__ __launch_bounds__(NTB) void k_batch(const int* __restrict__ x)
{
    extern __shared__ float dynsm[];
    __shared__ int   sidx[NN];
    __shared__ short spos[NN];
    __shared__ unsigned char sact[NN];
    __shared__ float s_inv[32];
    __shared__ int   s_rbD[32];
    __shared__ int   s_sh;

    const int b = blockIdx.x;
    const int tid = threadIdx.x, warp = tid >> 5, lane = tid & 31;

    if (tid < 32) {
        int cnt = 0;
        for (int base = 0; base < NN; base += 32) {
            int g = base + lane;
            int v = (x[b*NN + g] != 0);
            unsigned m = __ballot_sync(0xffffffffu, v);
            int p = cnt + __popc(m & ((1u << lane) - 1u));
            if (v) sidx[p] = g;
            spos[g] = (short)p;
            sact[g] = (unsigned char)v;
            cnt += __popc(m);
        }
        if (lane == 0) s_sh = cnt;
    }
    __syncthreads();
    const int s = s_sh;
    const bool fits = (s <= S_CAP);
    float* A  = fits ? dynsm            : &g_fbA [(size_t)b * PK_FULL];
    float* PB = fits ? (dynsm + PK_CAP) : &g_fbPB[(size_t)b * 32 * NN];
    const int pbw = fits ? PBW_SM : NN;

    for (int i = warp; i < s; i += NWB) {
        const float* Lrow = &g_L[sidx[i] * NN];
        const int rb = (i * (i + 1)) >> 1;
        const int glim = sidx[i] + 1;
        for (int g = lane; g < glim; g += 32) {
            float v = Lrow[g];
            if (sact[g]) A[rb + spos[g]] = v;
        }
    }
    __syncthreads();

    float lsum = 0.f;
    for (int j0 = 0; j0 < s; j0 += 32) {
        const int nbj = (s - j0 < 32) ? (s - j0) : 32;
        if (tid < nbj)
            s_rbD[tid] = (((j0 + tid) * (j0 + tid + 1)) >> 1) + j0;
        __syncthreads();

        if (warp == 0) {
            const int row = j0 + lane;
            const bool act = (lane < nbj);
            const int rbI = act ? ((row * (row + 1)) >> 1) : 0;
            float v[32];
#pragma unroll
            for (int k = 0; k < 32; ++k)
                v[k] = (act && k <= lane && k < nbj) ? A[rbI + j0 + k] : 0.f;

#pragma unroll
            for (int j = 0; j < 32; ++j) {
                if (j >= nbj) break;
                float dj = __shfl_sync(0xffffffffu, v[j], j);
                float d = sqrtf(dj);
                float inv = 1.f / d;
                if (lane == j) { v[j] = d; s_inv[j] = inv; }
                else if (lane > j) v[j] *= inv;
                float cj = (lane > j) ? v[j] : 0.f;
#pragma unroll
                for (int k = j + 1; k < 32; ++k) {
                    float cjk = __shfl_sync(0xffffffffu, cj, k);
                    v[k] -= cj * cjk;
                }
                if (lane == 0) lsum += logf(d);
            }
#pragma unroll
            for (int k = 0; k < 32; ++k)
                if (act && k <= lane && k < nbj) A[rbI + j0 + k] = v[k];
        }
        __syncthreads();

        const int j1 = j0 + 32;
        if (j1 >= s) break;
        const int nrows = s - j1;

        for (int i = j1 + tid; i < s; i += NTB) {
            const int rbI = (i * (i + 1)) >> 1;
            float v[32];
#pragma unroll
            for (int j = 0; j < 32; ++j) v[j] = A[rbI + j0 + j];
#pragma unroll
            for (int j = 0; j < 32; ++j) {
                float acc0 = v[j], acc1 = 0.f;
                const float* dr = &A[s_rbD[j]];
#pragma unroll
                for (int m = 0; m + 1 < j; m += 2) {
                    acc0 -= v[m]   * dr[m];
                    acc1 -= v[m+1] * dr[m+1];
                }
                if (j & 1) acc0 -= v[j-1] * dr[j-1];
                v[j] = (acc0 + acc1) * s_inv[j];
            }
            const int col = i - j1;
#pragma unroll
            for (int j = 0; j < 32; ++j) PB[j * pbw + col] = v[j];
        }
        __syncthreads();

        const int RT = (nrows + 7) >> 3;
        for (int ti = warp; ti < RT; ti += NWB) {
            const int ar = 8 * ti;
            const int ktmax = 2 * ti + 2;
            for (int kt = lane; kt < ktmax; kt += 32) {
                const int bc = 4 * kt;
                float acc[8][4];
#pragma unroll
                for (int qr = 0; qr < 8; ++qr)
#pragma unroll
                    for (int qc = 0; qc < 4; ++qc) acc[qr][qc] = 0.f;
#pragma unroll
                for (int j = 0; j < 32; ++j) {
                    const float* pr = &PB[j * pbw];
                    float4 a0 = *(const float4*)&pr[ar];
                    float4 a1 = *(const float4*)&pr[ar + 4];
                    float4 bv = *(const float4*)&pr[bc];
                    float av[8] = {a0.x,a0.y,a0.z,a0.w,a1.x,a1.y,a1.z,a1.w};
                    float bb[4] = {bv.x,bv.y,bv.z,bv.w};
#pragma unroll
                    for (int qr = 0; qr < 8; ++qr)
#pragma unroll
                        for (int qc = 0; qc < 4; ++qc)
                            acc[qr][qc] += av[qr] * bb[qc];
                }
#pragma unroll
                for (int qr = 0; qr < 8; ++qr) {
                    const int r = j1 + ar + qr;
                    if (r < s) {
                        const int rb = (r * (r + 1)) >> 1;
#pragma unroll
                        for (int qc = 0; qc < 4; ++qc) {
                            const int c = j1 + bc + qc;
                            if (c <= r) A[rb + c] -= acc[qr][qc];
                        }
                    }
                }
            }
        }
        __syncthreads();
    }
    if (tid == 0) g_bres[b] = 2.f * lsum;
}

// =====================================================================
// k_zbig: single-CTA in-place Cholesky of g_Z (512x512, lower), with the
// solved 32-col panel (PB) in shared memory. Phase C (dominant work)
// reads only smem; trailing updates write straight to L2-resident g_Z.
// Structure cloned from k_batch (the one kernel whose cost model holds).
// =====================================================================
__global__ __launch_bounds__(512) void k_zbig()
{
    extern __shared__ float PB[];             // 32 x ZPBW
    __shared__ float s_diag[32*33];           // factored diag block (lower)
    __shared__ float s_inv[32];
    const int tid = threadIdx.x, warp = tid >> 5, lane = tid & 31;
    float* A = g_Z;                           // factor lower in place

    float lsum = 0.f;
#pragma unroll 1
    for (int j0 = 0; j0 < NN; j0 += 32) {
        // ---- Phase A: warp0 factors 32x32 diag block (registers+shfl) ----
        if (warp == 0) {
            const int row = j0 + lane;
            float v[32];
#pragma unroll
            for (int k = 0; k < 32; ++k)
                v[k] = (k <= lane) ? A[row*NN + j0 + k] : 0.f;
#pragma unroll
            for (int j = 0; j < 32; ++j) {
                float dj = __shfl_sync(0xffffffffu, v[j], j);
                float d = sqrtf(dj);
                float inv = 1.f / d;
                if (lane == j) { v[j] = d; s_inv[j] = inv; }
                else if (lane > j) v[j] *= inv;
                float cj = (lane > j) ? v[j] : 0.f;
#pragma unroll
                for (int k = j + 1; k < 32; ++k) {
                    float cjk = __shfl_sync(0xffffffffu, cj, k);
                    v[k] -= cj * cjk;
                }
                if (lane == 0) lsum += logf(d);
            }
            // stash factored block in smem for Phase B (lower part valid)
#pragma unroll
            for (int k = 0; k < 32; ++k)
                s_diag[lane*33 + k] = (k <= lane) ? v[k] : 0.f;
        }
        __syncthreads();

        const int j1 = j0 + 32;
        if (j1 >= NN) break;
        const int nrows = NN - j1;

        // ---- Phase B: rows j1..511 solve vs s_diag; write PB (smem) ----
        for (int i = j1 + tid; i < NN; i += 512) {
            float v[32];
#pragma unroll
            for (int j = 0; j < 32; ++j) v[j] = A[i*NN + j0 + j];
#pragma unroll
            for (int j = 0; j < 32; ++j) {
                float acc0 = v[j], acc1 = 0.f;
                const float* dr = &s_diag[j*33];
#pragma unroll
                for (int m = 0; m + 1 < j; m += 2) {
                    acc0 -= v[m]   * dr[m];
                    acc1 -= v[m+1] * dr[m+1];
                }
                if (j & 1) acc0 -= v[j-1] * dr[j-1];
                v[j] = (acc0 + acc1) * s_inv[j];
            }
            const int col = i - j1;
#pragma unroll
            for (int j = 0; j < 32; ++j) PB[j * ZPBW + col] = v[j];
        }
        __syncthreads();

        // ---- Phase C: SYRK trailing from PB (smem), accumulate to g_Z ----
        const int RT = (nrows + 7) >> 3;
        for (int ti = warp; ti < RT; ti += 16) {
            const int ar = 8 * ti;
            const int ktmax = 2 * ti + 2;
            for (int kt = lane; kt < ktmax; kt += 32) {
                const int bc = 4 * kt;
                float acc[8][4];
#pragma unroll
                for (int qr = 0; qr < 8; ++qr)
#pragma unroll
                    for (int qc = 0; qc < 4; ++qc) acc[qr][qc] = 0.f;
#pragma unroll
                for (int j = 0; j < 32; ++j) {
                    const float* pr = &PB[j * ZPBW];
                    float4 a0 = *(const float4*)&pr[ar];
                    float4 a1 = *(const float4*)&pr[ar + 4];
                    float4 bv = *(const float4*)&pr[bc];
                    float av[8] = {a0.x,a0.y,a0.z,a0.w,a1.x,a1.y,a1.z,a1.w};
                    float bb[4] = {bv.x,bv.y,bv.z,bv.w};
#pragma unroll
                    for (int qr = 0; qr < 8; ++qr)
#pragma unroll
                        for (int qc = 0; qc < 4; ++qc)
                            acc[qr][qc] += av[qr] * bb[qc];
                }
#pragma unroll
                for (int qr = 0; qr < 8; ++qr) {
                    const int r = j1 + ar + qr;
                    if (r < NN) {
#pragma unroll
                        for (int qc = 0; qc < 4; ++qc) {
                            const int c = j1 + bc + qc;
                            if (c <= r) A[r*NN + c] -= acc[qr][qc];
                        }
                    }
                }
            }
        }
        __syncthreads();
    }
    if (tid == 0) g_zlog = 2.f * lsum;
}

// =====================================================================
__global__ void k_combine(float* __restrict__ out)
{
    if (threadIdx.x < NBATCH)
        out[threadIdx.x] = g_bres[threadIdx.x] - g_zlog;
}

// =====================================================================
extern "C" void kernel_launch(void* const* d_in, const int* in_sizes, int n_in,
                              void* d_out, int out_size)
{
    const int* x = (const int*)d_in[0];
    const float* Bm = (const float*)d_in[1];
    if (in_sizes[0] == NN*NN && in_sizes[1] == NBATCH*NN) {
        x  = (const int*)d_in[1];
        Bm = (const float*)d_in[0];
    }
    float* out = (float*)d_out;

    cudaFuncSetAttribute(k_batch, cudaFuncAttributeMaxDynamicSharedMemorySize, DYN_B);
    cudaFuncSetAttribute(k_zbig,  cudaFuncAttributeMaxDynamicSharedMemorySize, ZB_SMEM);

    cudaStream_t s2;
    cudaStreamCreateWithFlags(&s2, cudaStreamNonBlocking);
    cudaEvent_t eg, e2;
    cudaEventCreateWithFlags(&eg, cudaEventDisableTiming);
    cudaEventCreateWithFlags(&e2, cudaEventDisableTiming);

    k_gemm<<<dim3(8,8), 256>>>(Bm);                  // #1 (main)
    cudaEventRecord(eg, 0);
    cudaStreamWaitEvent(s2, eg, 0);
    k_zbig<<<1, 512, ZB_SMEM, s2>>>();               // #2 (s2)
    cudaEventRecord(e2, s2);
    k_batch<<<NBATCH, NTB, DYN_B>>>(x);              // #3 (main)
    cudaStreamWaitEvent(0, e2, 0);
    k_combine<<<1, 128>>>(out);                      // #4 (main)

    cudaStreamCaptureStatus st = cudaStreamCaptureStatusNone;
    cudaStreamIsCapturing(0, &st);
    if (st == cudaStreamCaptureStatusNone) {
        cudaEventDestroy(eg); cudaEventDestroy(e2);
        cudaStreamDestroy(s2);
    }
}

// round 16
// speedup vs baseline: 3.9266x; 3.9266x over previous
#include <cuda_runtime.h>
#include <cuda_bf16.h>
#include <math.h>

#define NN 512
#define NBATCH 128
#define EPS 1e-8f
#define S_CAP 304
#define PK_CAP ((S_CAP*(S_CAP+1))/2)
#define PBW_SM (S_CAP-32)
#define PK_FULL ((NN*(NN+1))/2)
#define NTB 512
#define NWB 16
#define NT 512
#define NW 16
#define DYN_B ((PK_CAP + 32*PBW_SM)*4)
#define U65 (64*65)
#define ZF_SMEM (5*U65*4)                 /* 83200 B */

// ---------------- device scratch ----------------
__device__ float g_L[NN*NN];
__device__ float g_Z[NN*NN];
__device__ float g_zpart[8];
__device__ float g_bres[NBATCH];
__device__ int   g_zflagB[8];
__device__ __align__(16) float g_fbA[(size_t)NBATCH * PK_FULL];
__device__ __align__(16) float g_fbPB[(size_t)NBATCH * 32 * NN];

// =====================================================================
// K1: L = B^T B + eps I ; Z = L + I.  Also zeroes the zf flags.
// =====================================================================
__global__ __launch_bounds__(256) void k_gemm(const float* __restrict__ B)
{
    __shared__ float SA[16][64];
    __shared__ float SB[16][64];
    const int tid = threadIdx.x;
    const int tx = tid & 15, ty = tid >> 4;
    const int i0 = blockIdx.y * 64, j0 = blockIdx.x * 64;

    if (blockIdx.x == 0 && blockIdx.y == 0 && tid < 8) g_zflagB[tid] = 0;

    float acc[4][4];
#pragma unroll
    for (int r = 0; r < 4; ++r)
#pragma unroll
        for (int c = 0; c < 4; ++c) acc[r][c] = 0.f;

    for (int kc = 0; kc < NN; kc += 16) {
        for (int e = tid; e < 16*64; e += 256) {
            int kk = e >> 6, ii = e & 63;
            SA[kk][ii] = B[(kc+kk)*NN + i0 + ii];
            SB[kk][ii] = B[(kc+kk)*NN + j0 + ii];
        }
        __syncthreads();
#pragma unroll
        for (int kk = 0; kk < 16; ++kk) {
            float a[4], bb[4];
#pragma unroll
            for (int r = 0; r < 4; ++r) a[r]  = SA[kk][ty*4 + r];
#pragma unroll
            for (int c = 0; c < 4; ++c) bb[c] = SB[kk][tx*4 + c];
#pragma unroll
            for (int r = 0; r < 4; ++r)
#pragma unroll
                for (int c = 0; c < 4; ++c) acc[r][c] += a[r] * bb[c];
        }
        __syncthreads();
    }
#pragma unroll
    for (int r = 0; r < 4; ++r)
#pragma unroll
        for (int c = 0; c < 4; ++c) {
            int gi = i0 + ty*4 + r, gj = j0 + tx*4 + c;
            float v = acc[r][c] + ((gi == gj) ? EPS : 0.f);
            g_L[gi*NN + gj] = v;
            g_Z[gi*NN + gj] = v + ((gi == gj) ? 1.f : 0.f);
        }
}

// =====================================================================
// Per-batch blocked Cholesky (nb=32). (unchanged, R11)
// =====================================================================
__global__ __launch_bounds__(NTB) void k_batch(const int* __restrict__ x)
{
    extern __shared__ float dynsm[];
    __shared__ int   sidx[NN];
    __shared__ short spos[NN];
    __shared__ unsigned char sact[NN];
    __shared__ float s_inv[32];
    __shared__ int   s_rbD[32];
    __shared__ int   s_sh;

    const int b = blockIdx.x;
    const int tid = threadIdx.x, warp = tid >> 5, lane = tid & 31;

    if (tid < 32) {
        int cnt = 0;
        for (int base = 0; base < NN; base += 32) {
            int g = base + lane;
            int v = (x[b*NN + g] != 0);
            unsigned m = __ballot_sync(0xffffffffu, v);
            int p = cnt + __popc(m & ((1u << lane) - 1u));
            if (v) sidx[p] = g;
            spos[g] = (short)p;
            sact[g] = (unsigned char)v;
            cnt += __popc(m);
        }
        if (lane == 0) s_sh = cnt;
    }
    __syncthreads();
    const int s = s_sh;
    const bool fits = (s <= S_CAP);
    float* A  = fits ? dynsm            : &g_fbA [(size_t)b * PK_FULL];
    float* PB = fits ? (dynsm + PK_CAP) : &g_fbPB[(size_t)b * 32 * NN];
    const int pbw = fits ? PBW_SM : NN;

    for (int i = warp; i < s; i += NWB) {
        const float* Lrow = &g_L[sidx[i] * NN];
        const int rb = (i * (i + 1)) >> 1;
        const int glim = sidx[i] + 1;
        for (int g = lane; g < glim; g += 32) {
            float v = Lrow[g];
            if (sact[g]) A[rb + spos[g]] = v;
        }
    }
    __syncthreads();

    float lsum = 0.f;
    for (int j0 = 0; j0 < s; j0 += 32) {
        const int nbj = (s - j0 < 32) ? (s - j0) : 32;
        if (tid < nbj)
            s_rbD[tid] = (((j0 + tid) * (j0 + tid + 1)) >> 1) + j0;
        __syncthreads();

        if (warp == 0) {
            const int row = j0 + lane;
            const bool act = (lane < nbj);
            const int rbI = act ? ((row * (row + 1)) >> 1) : 0;
            float v[32];
#pragma unroll
            for (int k = 0; k < 32; ++k)
                v[k] = (act && k <= lane && k < nbj) ? A[rbI + j0 + k] : 0.f;

#pragma unroll
            for (int j = 0; j < 32; ++j) {
                if (j >= nbj) break;
                float dj = __shfl_sync(0xffffffffu, v[j], j);
                float d = sqrtf(dj);
                float inv = 1.f / d;
                if (lane == j) { v[j] = d; s_inv[j] = inv; }
                else if (lane > j) v[j] *= inv;
                float cj = (lane > j) ? v[j] : 0.f;
#pragma unroll
                for (int k = j + 1; k < 32; ++k) {
                    float cjk = __shfl_sync(0xffffffffu, cj, k);
                    v[k] -= cj * cjk;
                }
                if (lane == 0) lsum += logf(d);
            }
#pragma unroll
            for (int k = 0; k < 32; ++k)
                if (act && k <= lane && k < nbj) A[rbI + j0 + k] = v[k];
        }
        __syncthreads();

        const int j1 = j0 + 32;
        if (j1 >= s) break;
        const int nrows = s - j1;

        for (int i = j1 + tid; i < s; i += NTB) {
            const int rbI = (i * (i + 1)) >> 1;
            float v[32];
#pragma unroll
            for (int j = 0; j < 32; ++j) v[j] = A[rbI + j0 + j];
#pragma unroll
            for (int j = 0; j < 32; ++j) {
                float acc0 = v[j], acc1 = 0.f;
                const float* dr = &A[s_rbD[j]];
#pragma unroll
                for (int m = 0; m + 1 < j; m += 2) {
                    acc0 -= v[m]   * dr[m];
                    acc1 -= v[m+1] * dr[m+1];
                }
                if (j & 1) acc0 -= v[j-1] * dr[j-1];
                v[j] = (acc0 + acc1) * s_inv[j];
            }
            const int col = i - j1;
#pragma unroll
            for (int j = 0; j < 32; ++j) PB[j * pbw + col] = v[j];
        }
        __syncthreads();

        const int RT = (nrows + 7) >> 3;
        for (int ti = warp; ti < RT; ti += NWB) {
            const int ar = 8 * ti;
            const int ktmax = 2 * ti + 2;
            for (int kt = lane; kt < ktmax; kt += 32) {
                const int bc = 4 * kt;
                float acc[8][4];
#pragma unroll
                for (int qr = 0; qr < 8; ++qr)
#pragma unroll
                    for (int qc = 0; qc < 4; ++qc) acc[qr][qc] = 0.f;
#pragma unroll
                for (int j = 0; j < 32; ++j) {
                    const float* pr = &PB[j * pbw];
                    float4 a0 = *(const float4*)&pr[ar];
                    float4 a1 = *(const float4*)&pr[ar + 4];
                    float4 bv = *(const float4*)&pr[bc];
                    float av[8] = {a0.x,a0.y,a0.z,a0.w,a1.x,a1.y,a1.z,a1.w};
                    float bb[4] = {bv.x,bv.y,bv.z,bv.w};
#pragma unroll
                    for (int qr = 0; qr < 8; ++qr)
#pragma unroll
                        for (int qc = 0; qc < 4; ++qc)
                            acc[qr][qc] += av[qr] * bb[qc];
                }
#pragma unroll
                for (int qr = 0; qr < 8; ++qr) {
                    const int r = j1 + ar + qr;
                    if (r < s) {
                        const int rb = (r * (r + 1)) >> 1;
#pragma unroll
                        for (int qc = 0; qc < 4; ++qc) {
                            const int c = j1 + bc + qc;
                            if (c <= r) A[rb + c] -= acc[qr][qc];
                        }
                    }
                }
            }
        }
        __syncthreads();
    }
    if (tid == 0) g_bres[b] = 2.f * lsum;
}

// =====================================================================
// zpanelN(0): factor panel 0 over rows 0..127 (unchanged from R11).
// =====================================================================
__global__ __launch_bounds__(NT) void k_zpanelN(int p)
{
    extern __shared__ float T[];
    __shared__ float s_inv[32];
    const int nr_full = NN - 64 * p;
    const int nr = (nr_full < 128) ? nr_full : 128;
    const int tid = threadIdx.x, warp = tid >> 5, lane = tid & 31;

    for (int r = warp; r < nr; r += NW) {
        const float* src = &g_Z[(64*p + r)*NN + 64*p];
        float* dst = &T[r*65];
        for (int j = lane; j < 64; j += 32) dst[j] = src[j];
    }
    __syncthreads();

    float lsum = 0.f;
    for (int cb = 0; cb < 64; cb += 32) {
        if (warp == 0) {
            float v[32];
#pragma unroll
            for (int k = 0; k < 32; ++k)
                v[k] = (k <= lane) ? T[(cb+lane)*65 + cb + k] : 0.f;
#pragma unroll
            for (int j = 0; j < 32; ++j) {
                float dj = __shfl_sync(0xffffffffu, v[j], j);
                float d = sqrtf(dj);
                float inv = 1.f / d;
                if (lane == j) { v[j] = d; s_inv[j] = inv; }
                else if (lane > j) v[j] *= inv;
                float cj = (lane > j) ? v[j] : 0.f;
#pragma unroll
                for (int k = j + 1; k < 32; ++k) {
                    float cjk = __shfl_sync(0xffffffffu, cj, k);
                    v[k] -= cj * cjk;
                }
                if (lane == 0) lsum += logf(d);
            }
#pragma unroll
            for (int k = 0; k < 32; ++k)
                if (k <= lane) T[(cb+lane)*65 + cb + k] = v[k];
        }
        __syncthreads();

        const int r1 = cb + 32;
        for (int i = r1 + tid; i < nr; i += NT) {
            float* row = &T[i*65 + cb];
            float v[32];
#pragma unroll
            for (int j = 0; j < 32; ++j) v[j] = row[j];
#pragma unroll
            for (int j = 0; j < 32; ++j) {
                float acc0 = v[j], acc1 = 0.f;
                const float* dr = &T[(cb+j)*65 + cb];
#pragma unroll
                for (int m = 0; m + 1 < j; m += 2) {
                    acc0 -= v[m]   * dr[m];
                    acc1 -= v[m+1] * dr[m+1];
                }
                if (j & 1) acc0 -= v[j-1] * dr[j-1];
                v[j] = (acc0 + acc1) * s_inv[j];
            }
#pragma unroll
            for (int j = 0; j < 32; ++j) row[j] = v[j];
        }
        __syncthreads();

        if (cb == 0) {
            const int nrows2 = nr - 32;
            const int RT = (nrows2 + 15) >> 4;
            const int sub = lane >> 3;
            const int ktc = lane & 7;
            for (int ti = warp; ti < RT; ti += NW) {
                const int r0 = 32 + ti*16 + sub*4;
                const int c0 = 32 + ktc*4;
                float acc[4][4];
#pragma unroll
                for (int qr = 0; qr < 4; ++qr)
#pragma unroll
                    for (int qc = 0; qc < 4; ++qc) acc[qr][qc] = 0.f;
#pragma unroll
                for (int j = 0; j < 32; ++j) {
                    float a[4], bb[4];
#pragma unroll
                    for (int q = 0; q < 4; ++q) {
                        int r = r0 + q; if (r > nr - 1) r = nr - 1;
                        a[q] = T[r*65 + j];
                    }
#pragma unroll
                    for (int q = 0; q < 4; ++q) bb[q] = T[(c0+q)*65 + j];
#pragma unroll
                    for (int qr = 0; qr < 4; ++qr)
#pragma unroll
                        for (int qc = 0; qc < 4; ++qc)
                            acc[qr][qc] += a[qr] * bb[qc];
                }
#pragma unroll
                for (int qr = 0; qr < 4; ++qr) {
                    const int r = r0 + qr;
#pragma unroll
                    for (int qc = 0; qc < 4; ++qc) {
                        const int c = c0 + qc;
                        if (r < nr && c <= r)
                            T[r*65 + c] -= acc[qr][qc];
                    }
                }
            }
        }
        __syncthreads();
    }

    for (int r = warp; r < nr; r += NW) {
        float* dst = &g_Z[(64*p + r)*NN + 64*p];
        int jmax = (r < 63) ? r : 63;
        for (int j = lane; j <= jmax; j += 32) dst[j] = T[r*65 + j];
    }
    if (tid == 0) g_zpart[p] = 2.f * lsum;
}

// =====================================================================
// zf(q): fused step. grid = 7-q CTAs, 512 thr.
//  CTA l>=1 (i=q+1+l): solve Xi=(i,q) vs L11(q); write (i,q);
//      (i,q+1) -= Xi·Xq1^T [+ fold: X(i,q-1)·X(q+1,q-1)^T  if q>0];
//      CTA l==1 sets flagB[q] when done.
//  CTA 0: D=(q+1,q+1) in smem; D -= Xq1·Xq1^T [+ Xq1m·Xq1m^T];
//      factor D (logdet -> g_zpart[q+1], write lower);
//      if q<=5: wait flagB[q]; load (q+2,q+1) (__ldcg); solve 64 rows
//      vs D (two-stage + inner GEMM); write back.
// =====================================================================
__global__ __launch_bounds__(512) void k_zf(int q)
{
    extern __shared__ float sm[];
    const int tid = threadIdx.x, warp = tid >> 5, lane = tid & 31;

    if (blockIdx.x > 0) {
        // ---------------- solve CTA ----------------
        const int i = q + 1 + blockIdx.x;          // q+2..7
        float* L11 = sm;
        float* Xq1 = sm + U65;
        float* Ai  = sm + 2*U65;
        float* Xim = sm + 3*U65;
        float* Xqm = sm + 4*U65;
        __shared__ float s_inv[64];

        for (int e = tid; e < 64*64; e += 512) {
            int r = e >> 6, c = e & 63;
            L11[r*65 + c] = g_Z[(64*q + r)*NN + 64*q + c];
            Xq1[r*65 + c] = g_Z[(64*(q+1) + r)*NN + 64*q + c];   // solved
            Ai [r*65 + c] = g_Z[(64*i + r)*NN + 64*q + c];       // raw
        }
        if (q > 0) {
            for (int e = tid; e < 64*64; e += 512) {
                int r = e >> 6, c = e & 63;
                Xim[r*65 + c] = g_Z[(64*i + r)*NN + 64*(q-1) + c];     // solved
                Xqm[r*65 + c] = g_Z[(64*(q+1) + r)*NN + 64*(q-1) + c]; // solved
            }
        }
        if (tid < 64)
            s_inv[tid] = 1.f / g_Z[(64*q + tid)*NN + 64*q + tid];
        __syncthreads();

        // solve Ai rows (R11 inline)
        if (tid < 64) {
            float* row = &Ai[tid*65];
            float x1[32], v[32];
#pragma unroll
            for (int j = 0; j < 32; ++j) x1[j] = row[j];
#pragma unroll
            for (int j = 0; j < 32; ++j) {
                float acc = x1[j];
                const float* dr = &L11[j*65];
#pragma unroll
                for (int m = 0; m < j; ++m) acc -= x1[m] * dr[m];
                x1[j] = acc * s_inv[j];
            }
#pragma unroll
            for (int j = 0; j < 32; ++j) v[j] = row[32 + j];
#pragma unroll
            for (int j = 0; j < 32; ++j) {
                float acc = v[j];
                const float* dr = &L11[(32+j)*65];
#pragma unroll
                for (int m = 0; m < 32; ++m) acc -= x1[m] * dr[m];
#pragma unroll
                for (int m = 0; m < j; ++m) acc -= v[m] * dr[32 + m];
                v[j] = acc * s_inv[32 + j];
            }
#pragma unroll
            for (int j = 0; j < 32; ++j) { row[j] = x1[j]; row[32+j] = v[j]; }
        }
        __syncthreads();
        for (int e = tid; e < 64*64; e += 512) {
            int r = e >> 6, c = e & 63;
            g_Z[(64*i + r)*NN + 64*q + c] = Ai[r*65 + c];
        }

        // (i,q+1) -= Ai·Xq1^T [+ Xim·Xqm^T]
        {
            const int tx = tid & 15, ty = tid >> 4;
            float acc[2][4];
#pragma unroll
            for (int r = 0; r < 2; ++r)
#pragma unroll
                for (int c = 0; c < 4; ++c) acc[r][c] = 0.f;
#pragma unroll
            for (int k = 0; k < 64; ++k) {
                float a[2], bb[4];
#pragma unroll
                for (int r = 0; r < 2; ++r) a[r]  = Ai[(ty*2 + r)*65 + k];
#pragma unroll
                for (int c = 0; c < 4; ++c) bb[c] = Xq1[(tx*4 + c)*65 + k];
#pragma unroll
                for (int r = 0; r < 2; ++r)
#pragma unroll
                    for (int c = 0; c < 4; ++c) acc[r][c] += a[r] * bb[c];
            }
            if (q > 0) {
#pragma unroll
                for (int k = 0; k < 64; ++k) {
                    float a[2], bb[4];
#pragma unroll
                    for (int r = 0; r < 2; ++r) a[r]  = Xim[(ty*2 + r)*65 + k];
#pragma unroll
                    for (int c = 0; c < 4; ++c) bb[c] = Xqm[(tx*4 + c)*65 + k];
#pragma unroll
                    for (int r = 0; r < 2; ++r)
#pragma unroll
                        for (int c = 0; c < 4; ++c) acc[r][c] += a[r] * bb[c];
                }
            }
#pragma unroll
            for (int r = 0; r < 2; ++r)
#pragma unroll
                for (int c = 0; c < 4; ++c)
                    g_Z[(64*i + ty*2 + r)*NN + 64*(q+1) + tx*4 + c] -= acc[r][c];
        }

        if (blockIdx.x == 1) {
            __syncthreads();
            __threadfence();
            if (tid == 0) atomicExch(&g_zflagB[q], 1);
        }
        return;
    }

    // ---------------- CTA 0: diag update + factor + deep-row solve ----------------
    {
        float* Xq1 = sm;                 // X(q+1,q) solved
        float* Xqm = sm + U65;           // X(q+1,q-1) solved (q>0)
        float* T   = sm + 2*U65;         // 128 x 65: rows 0..63 = D
        __shared__ float s_inv64[64];
        float lsum = 0.f;

        for (int e = tid; e < 64*64; e += 512) {
            int r = e >> 6, c = e & 63;
            Xq1[r*65 + c] = g_Z[(64*(q+1) + r)*NN + 64*q + c];
            T  [r*65 + c] = g_Z[(64*(q+1) + r)*NN + 64*(q+1) + c];
        }
        if (q > 0) {
            for (int e = tid; e < 64*64; e += 512) {
                int r = e >> 6, c = e & 63;
                Xqm[r*65 + c] = g_Z[(64*(q+1) + r)*NN + 64*(q-1) + c];
            }
        }
        __syncthreads();

        // D -= Xq1·Xq1^T [+ Xqm·Xqm^T]
        {
            const int tx = tid & 15, ty = tid >> 4;
            float acc[2][4];
#pragma unroll
            for (int r = 0; r < 2; ++r)
#pragma unroll
                for (int c = 0; c < 4; ++c) acc[r][c] = 0.f;
#pragma unroll
            for (int k = 0; k < 64; ++k) {
                float a[2], bb[4];
#pragma unroll
                for (int r = 0; r < 2; ++r) a[r]  = Xq1[(ty*2 + r)*65 + k];
#pragma unroll
                for (int c = 0; c < 4; ++c) bb[c] = Xq1[(tx*4 + c)*65 + k];
#pragma unroll
                for (int r = 0; r < 2; ++r)
#pragma unroll
                    for (int c = 0; c < 4; ++c) acc[r][c] += a[r] * bb[c];
            }
            if (q > 0) {
#pragma unroll
                for (int k = 0; k < 64; ++k) {
                    float a[2], bb[4];
#pragma unroll
                    for (int r = 0; r < 2; ++r) a[r]  = Xqm[(ty*2 + r)*65 + k];
#pragma unroll
                    for (int c = 0; c < 4; ++c) bb[c] = Xqm[(tx*4 + c)*65 + k];
#pragma unroll
                    for (int r = 0; r < 2; ++r)
#pragma unroll
                        for (int c = 0; c < 4; ++c) acc[r][c] += a[r] * bb[c];
                }
            }
#pragma unroll
            for (int r = 0; r < 2; ++r)
#pragma unroll
                for (int c = 0; c < 4; ++c)
                    T[(ty*2 + r)*65 + tx*4 + c] -= acc[r][c];
        }
        __syncthreads();

        // factor D = T[0..63] (nr = 64, zpanelN flow)
        for (int cb = 0; cb < 64; cb += 32) {
            if (warp == 0) {
                float v[32];
#pragma unroll
                for (int k = 0; k < 32; ++k)
                    v[k] = (k <= lane) ? T[(cb+lane)*65 + cb + k] : 0.f;
#pragma unroll
                for (int j = 0; j < 32; ++j) {
                    float dj = __shfl_sync(0xffffffffu, v[j], j);
                    float d = sqrtf(dj);
                    float inv = 1.f / d;
                    if (lane == j) { v[j] = d; s_inv64[cb + j] = inv; }
                    else if (lane > j) v[j] *= inv;
                    float cj = (lane > j) ? v[j] : 0.f;
#pragma unroll
                    for (int k = j + 1; k < 32; ++k) {
                        float cjk = __shfl_sync(0xffffffffu, cj, k);
                        v[k] -= cj * cjk;
                    }
                    if (lane == 0) lsum += logf(d);
                }
#pragma unroll
                for (int k = 0; k < 32; ++k)
                    if (k <= lane) T[(cb+lane)*65 + cb + k] = v[k];
            }
            __syncthreads();

            if (cb == 0) {
                // rows 32..63 solve vs D11
                if (tid < 32) {
                    const int i2 = 32 + tid;
                    float v[32];
#pragma unroll
                    for (int j = 0; j < 32; ++j) v[j] = T[i2*65 + j];
#pragma unroll
                    for (int j = 0; j < 32; ++j) {
                        float acc = v[j];
                        const float* dr = &T[j*65];
#pragma unroll
                        for (int m = 0; m < j; ++m) acc -= v[m] * dr[m];
                        v[j] = acc * s_inv64[j];
                    }
#pragma unroll
                    for (int j = 0; j < 32; ++j) T[i2*65 + j] = v[j];
                }
                __syncthreads();
                // D22' -= X X^T
                {
                    const int r  = 32 + (tid >> 4);
                    const int c0 = 32 + ((tid & 15) << 1);
                    float a0 = 0.f, a1 = 0.f;
#pragma unroll
                    for (int k = 0; k < 32; ++k) {
                        float ar = T[r*65 + k];
                        a0 += ar * T[c0*65 + k];
                        a1 += ar * T[(c0+1)*65 + k];
                    }
                    T[r*65 + c0]     -= a0;
                    T[r*65 + c0 + 1] -= a1;
                }
                __syncthreads();
            }
        }

        // write factored (q+1,q+1) lower + logdet
        for (int e = tid; e < 64*64; e += 512) {
            int r = e >> 6, c = e & 63;
            if (c <= r) g_Z[(64*(q+1) + r)*NN + 64*(q+1) + c] = T[r*65 + c];
        }
        if (tid == 0) g_zpart[q+1] = 2.f * lsum;

        if (q <= 5) {
            // wait for CTA1's (q+2,q+1) update
            if (tid == 0) { while (atomicAdd(&g_zflagB[q], 0) == 0) {} }
            __syncthreads();

            // load rows 64..127 = (q+2,q+1), bypass L1
            for (int e = tid; e < 64*64; e += 512) {
                int r = e >> 6, c = e & 63;
                T[(64 + r)*65 + c] =
                    __ldcg(&g_Z[(64*(q+2) + r)*NN + 64*(q+1) + c]);
            }
            __syncthreads();

            // solve rows 64..127 cols 0..31 vs D11
            if (tid < 64) {
                const int i2 = 64 + tid;
                float v[32];
#pragma unroll
                for (int j = 0; j < 32; ++j) v[j] = T[i2*65 + j];
#pragma unroll
                for (int j = 0; j < 32; ++j) {
                    float acc = v[j];
                    const float* dr = &T[j*65];
#pragma unroll
                    for (int m = 0; m < j; ++m) acc -= v[m] * dr[m];
                    v[j] = acc * s_inv64[j];
                }
#pragma unroll
                for (int j = 0; j < 32; ++j) T[i2*65 + j] = v[j];
            }
            __syncthreads();

            // rows 64..127 cols 32..63 -= (cols 0..31)·D21^T
            {
                const int r  = 64 + (tid >> 3);
                const int c0 = (tid & 7) * 4;
                float acc[4] = {0.f, 0.f, 0.f, 0.f};
#pragma unroll
                for (int k = 0; k < 32; ++k) {
                    float ar = T[r*65 + k];
#pragma unroll
                    for (int j = 0; j < 4; ++j)
                        acc[j] += ar * T[(32 + c0 + j)*65 + k];
                }
#pragma unroll
                for (int j = 0; j < 4; ++j)
                    T[r*65 + 32 + c0 + j] -= acc[j];
            }
            __syncthreads();

            // solve rows 64..127 cols 32..63 vs D22
            if (tid < 64) {
                const int i2 = 64 + tid;
                float v[32];
#pragma unroll
                for (int j = 0; j < 32; ++j) v[j] = T[i2*65 + 32 + j];
#pragma unroll
                for (int j = 0; j < 32; ++j) {
                    float acc = v[j];
                    const float* dr = &T[(32 + j)*65 + 32];
#pragma unroll
                    for (int m = 0; m < j; ++m) acc -= v[m] * dr[m];
                    v[j] = acc * s_inv64[32 + j];
                }
#pragma unroll
                for (int j = 0; j < 32; ++j) T[i2*65 + 32 + j] = v[j];
            }
            __syncthreads();

            // write back solved (q+2,q+1)
            for (int e = tid; e < 64*64; e += 512) {
                int r = e >> 6, c = e & 63;
                g_Z[(64*(q+2) + r)*NN + 64*(q+1) + c] = T[(64 + r)*65 + c];
            }
        }
    }
}

// =====================================================================
// zfar(j): apply panel j to columns j+3..7 (s3, 2 steps of slack)
// =====================================================================
__global__ __launch_bounds__(256) void k_zfar(int j)
{
    __shared__ float As[64][65];
    __shared__ float Bs[64][65];
    int l = blockIdx.x, bi = 0, bj = 0;
    for (int c = j + 3; c <= 7; ++c) {
        int cnt = 8 - c;
        if (l < cnt) { bj = c; bi = c + l; break; }
        l -= cnt;
    }
    const int tid = threadIdx.x;
    const int tx = tid & 15, ty = tid >> 4;

    for (int e = tid; e < 64*64; e += 256) {
        int r = e >> 6, k = e & 63;
        As[r][k] = g_Z[(64*bi + r)*NN + 64*j + k];
    }
    for (int e = tid; e < 64*64; e += 256) {
        int r = e >> 6, k = e & 63;
        Bs[r][k] = g_Z[(64*bj + r)*NN + 64*j + k];
    }
    __syncthreads();

    float acc[4][4];
#pragma unroll
    for (int r = 0; r < 4; ++r)
#pragma unroll
        for (int c = 0; c < 4; ++c) acc[r][c] = 0.f;
    for (int k = 0; k < 64; ++k) {
        float a[4], bb[4];
#pragma unroll
        for (int r = 0; r < 4; ++r) a[r]  = As[ty*4 + r][k];
#pragma unroll
        for (int c = 0; c < 4; ++c) bb[c] = Bs[tx*4 + c][k];
#pragma unroll
        for (int r = 0; r < 4; ++r)
#pragma unroll
            for (int c = 0; c < 4; ++c) acc[r][c] += a[r] * bb[c];
    }
#pragma unroll
    for (int r = 0; r < 4; ++r)
#pragma unroll
        for (int c = 0; c < 4; ++c)
            g_Z[(64*bi + ty*4 + r)*NN + 64*bj + tx*4 + c] -= acc[r][c];
}

// =====================================================================
__global__ void k_combine(float* __restrict__ out)
{
    __shared__ float z;
    if (threadIdx.x == 0) {
        float t = 0.f;
        for (int p = 0; p < 8; ++p) t += g_zpart[p];
        z = t;
    }
    __syncthreads();
    if (threadIdx.x < NBATCH)
        out[threadIdx.x] = g_bres[threadIdx.x] - z;
}

// =====================================================================
extern "C" void kernel_launch(void* const* d_in, const int* in_sizes, int n_in,
                              void* d_out, int out_size)
{
    const int* x = (const int*)d_in[0];
    const float* Bm = (const float*)d_in[1];
    if (in_sizes[0] == NN*NN && in_sizes[1] == NBATCH*NN) {
        x  = (const int*)d_in[1];
        Bm = (const float*)d_in[0];
    }
    float* out = (float*)d_out;

    cudaFuncSetAttribute(k_batch,   cudaFuncAttributeMaxDynamicSharedMemorySize, DYN_B);
    cudaFuncSetAttribute(k_zf,      cudaFuncAttributeMaxDynamicSharedMemorySize, ZF_SMEM);
    cudaFuncSetAttribute(k_zpanelN, cudaFuncAttributeMaxDynamicSharedMemorySize, 128*65*4);

    cudaStream_t s2, s3;
    cudaStreamCreateWithFlags(&s2, cudaStreamNonBlocking);
    cudaStreamCreateWithFlags(&s3, cudaStreamNonBlocking);
    cudaEvent_t eg, e2, es[5], efar[5];
    cudaEventCreateWithFlags(&eg, cudaEventDisableTiming);
    cudaEventCreateWithFlags(&e2, cudaEventDisableTiming);
    for (int i = 0; i < 5; ++i) {
        cudaEventCreateWithFlags(&es[i], cudaEventDisableTiming);
        cudaEventCreateWithFlags(&efar[i], cudaEventDisableTiming);
    }

    k_gemm<<<dim3(8,8), 256>>>(Bm);                       // #1 (main, zeroes flags)
    cudaEventRecord(eg, 0);
    cudaStreamWaitEvent(s2, eg, 0);
    k_zpanelN<<<1, NT, 128*65*4, s2>>>(0);                // #2 (s2)
    k_batch<<<NBATCH, NTB, DYN_B>>>(x);                   // #3 (main)
    k_zf<<<7, 512, ZF_SMEM, s2>>>(0);                     // #4 (s2) <- profiled
    cudaEventRecord(es[0], s2);
    cudaStreamWaitEvent(s3, es[0], 0);
    k_zfar<<<15, 256, 0, s3>>>(0);
    cudaEventRecord(efar[0], s3);

    for (int q = 1; q <= 6; ++q) {
        if (q >= 2) cudaStreamWaitEvent(s2, efar[q-2], 0);
        k_zf<<<7 - q, 512, ZF_SMEM, s2>>>(q);
        if (q <= 4) {
            cudaEventRecord(es[q], s2);
            cudaStreamWaitEvent(s3, es[q], 0);
            k_zfar<<<(5 - q) * (6 - q) / 2, 256, 0, s3>>>(q);
            cudaEventRecord(efar[q], s3);
        }
    }
    cudaEventRecord(e2, s2);
    cudaStreamWaitEvent(0, e2, 0);
    k_combine<<<1, 128>>>(out);                           // last (main)

    cudaStreamCaptureStatus st = cudaStreamCaptureStatusNone;
    cudaStreamIsCapturing(0, &st);
    if (st == cudaStreamCaptureStatusNone) {
        cudaEventDestroy(eg); cudaEventDestroy(e2);
        for (int i = 0; i < 5; ++i) { cudaEventDestroy(es[i]); cudaEventDestroy(efar[i]); }
        cudaStreamDestroy(s2); cudaStreamDestroy(s3);
    }
}